// round 2
// baseline (speedup 1.0000x reference)
#include <cuda_runtime.h>
#include <cuda_fp16.h>
#include <cstdint>

// ---------------- problem constants ----------------
#define DEGREE   3
#define NB       7
#define NKNOTS   11
#define BATCH    8192
#define IN_DIM   1024
#define OUT_DIM  1024
#define KDIM     (IN_DIM * 8)   // 8192: 7 basis cols + 1 linear col per input

// GEMM tiling (baseline-PTX path: mma.sync m16n8k16, no tcgen05 on compute_103)
#define BM 128
#define BN 256
#define BK 64
#define STAGES 3
#define KITERS (KDIM / BK)      // 128
#define THREADS 256

#define A_STAGE (BM * BK * 2)   // 16384 B  (128 rows x 128B)
#define B_STAGE (BN * BK * 2)   // 32768 B  (256 rows x 128B)
#define A_OFF 0
#define B_OFF (STAGES * A_STAGE)                       // 49152
#define SMEM_BYTES (B_OFF + STAGES * B_STAGE + 1024)   // 144KB + align slack

// ---------------- scratch (device globals; no cudaMalloc allowed) ----------------
__device__ __half g_A[(size_t)BATCH * KDIM];    // 128 MB
__device__ __half g_B[(size_t)OUT_DIM * KDIM];  // 16 MB

// ---------------- PTX helpers (baseline ISA only) ----------------
__device__ __forceinline__ uint32_t smem_u32(const void* p) {
    uint32_t a;
    asm("{ .reg .u64 t; cvta.to.shared.u64 t, %1; cvt.u32.u64 %0, t; }" : "=r"(a) : "l"(p));
    return a;
}
__device__ __forceinline__ void cp_async16(uint32_t sdst, const void* gsrc) {
    asm volatile("cp.async.cg.shared.global [%0], [%1], 16;" :: "r"(sdst), "l"(gsrc));
}
#define CP_COMMIT() asm volatile("cp.async.commit_group;" ::: "memory")
#define CP_WAIT(n)  asm volatile("cp.async.wait_group %0;" :: "n"(n) : "memory")

#define LDSM_X4(r0, r1, r2, r3, addr) \
    asm volatile("ldmatrix.sync.aligned.m8n8.x4.shared.b16 {%0,%1,%2,%3}, [%4];" \
                 : "=r"(r0), "=r"(r1), "=r"(r2), "=r"(r3) : "r"(addr))

#define MMA16816(d, a, b0v, b1v) \
    asm volatile("mma.sync.aligned.m16n8k16.row.col.f32.f16.f16.f32 " \
                 "{%0,%1,%2,%3}, {%4,%5,%6,%7}, {%8,%9}, {%0,%1,%2,%3};" \
                 : "+f"((d)[0]), "+f"((d)[1]), "+f"((d)[2]), "+f"((d)[3]) \
                 : "r"((a)[0]), "r"((a)[1]), "r"((a)[2]), "r"((a)[3]), \
                   "r"(b0v), "r"(b1v))

// ---------------- prep kernel 1: A[b, i*8+k] = basis_k(tanh(x)) , x ----------------
__global__ void build_a_kernel(const float* __restrict__ x, const float* __restrict__ knots) {
    int idx = blockIdx.x * blockDim.x + threadIdx.x;   // b*IN + i
    float kn[NKNOTS];
#pragma unroll
    for (int j = 0; j < NKNOTS; ++j) kn[j] = __ldg(&knots[j]);
    float xv = x[idx];
    float t = tanhf(xv);
    t = fminf(fmaxf(t, kn[0]), kn[NKNOTS - 1]);
    float bas[NB];
#pragma unroll
    for (int j = 0; j < NB; ++j)
        bas[j] = (t >= kn[j] && t < kn[j + 1]) ? 1.0f : 0.0f;
#pragma unroll
    for (int d = 1; d <= DEGREE; ++d) {
#pragma unroll
        for (int j = 0; j < NB; ++j) {
            float left  = (t - kn[j]) / (kn[j + d] - kn[j]);
            float right = (kn[j + d + 1] - t) / (kn[j + d + 1] - kn[j + 1]);
            float nxt = (j + 1 < NB) ? bas[j + 1] : 0.0f;
            bas[j] = left * bas[j] + right * nxt;   // ascending in-place is safe
        }
    }
    __half h[8];
#pragma unroll
    for (int k = 0; k < NB; ++k) h[k] = __float2half_rn(bas[k]);
    h[7] = __float2half_rn(xv);
    *reinterpret_cast<uint4*>(&g_A[(size_t)idx * 8]) = *reinterpret_cast<const uint4*>(h);
}

// ---------------- prep kernel 2: Bmat[o, i*8+k] = spline_w[i,o,k] , W[o,i] ----------------
__global__ void build_b_kernel(const float* __restrict__ sw, const float* __restrict__ W) {
    int idx = blockIdx.x * blockDim.x + threadIdx.x;   // o*IN + i
    int o = idx >> 10, i = idx & 1023;
    const float* s = sw + ((size_t)i * OUT_DIM + o) * NB;
    __half h[8];
#pragma unroll
    for (int k = 0; k < NB; ++k) h[k] = __float2half_rn(__ldg(&s[k]));
    h[7] = __float2half_rn(__ldg(&W[(size_t)o * IN_DIM + i]));
    *reinterpret_cast<uint4*>(&g_B[(size_t)o * KDIM + (size_t)i * 8]) = *reinterpret_cast<const uint4*>(h);
}

// ---------------- GEMM: out[M,N] = A[M,K] * Bmat[N,K]^T + bias ----------------
// warps: 2(M) x 4(N), warp tile 64x64; mma m16n8k16 row.col, fp32 accum.
__global__ void __launch_bounds__(THREADS, 1)
kan_gemm_kernel(float* __restrict__ out, const float* __restrict__ bias) {
    extern __shared__ char smem_raw[];
    const uint32_t S = (smem_u32(smem_raw) + 1023u) & ~1023u;

    const int tid  = threadIdx.x;
    const int wid  = tid >> 5;
    const int lane = tid & 31;
    const int wm   = wid >> 2;      // 0..1
    const int wn   = wid & 3;       // 0..3
    const int n0 = blockIdx.x * BN;
    const int m0 = blockIdx.y * BM;

    const __half* gA = g_A + (size_t)m0 * KDIM;
    const __half* gB = g_B + (size_t)n0 * KDIM;

    // ---- async stage loader: swizzled rows of 128B (SW128: X ^= (row&7)*16) ----
    auto load_stage = [&](int it, int buf) {
        const int k0 = it * BK;
        const uint32_t ab = S + A_OFF + buf * A_STAGE;
#pragma unroll
        for (int t = 0; t < 4; ++t) {               // A: 1024 chunks of 16B
            int ch = tid + t * THREADS;
            int row = ch >> 3, cc = ch & 7;
            cp_async16(ab + row * 128 + ((cc * 16) ^ ((row & 7) * 16)),
                       gA + (size_t)row * KDIM + k0 + cc * 8);
        }
        const uint32_t bb = S + B_OFF + buf * B_STAGE;
#pragma unroll
        for (int t = 0; t < 8; ++t) {               // B: 2048 chunks of 16B
            int ch = tid + t * THREADS;
            int row = ch >> 3, cc = ch & 7;
            cp_async16(bb + row * 128 + ((cc * 16) ^ ((row & 7) * 16)),
                       gB + (size_t)row * KDIM + k0 + cc * 8);
        }
        CP_COMMIT();
    };

    // ---- precompute per-lane ldmatrix addressing ----
    // A: x4 over m16 x k16. lane l -> row = mi*16 + (l&15); k-half-block = l>>4.
    uint32_t aRow[4], aXor[4];
#pragma unroll
    for (int mi = 0; mi < 4; ++mi) {
        int row = wm * 64 + mi * 16 + (lane & 15);
        aRow[mi] = (uint32_t)(row * 128);
        aXor[mi] = (uint32_t)((row & 7) * 16);
    }
    const uint32_t aK = ((lane >> 4) * 16);

    // B: x4 over n16 x k16. lane l -> n = g*16 + ((l>>4)<<3) + (l&7); k-block = (l>>3)&1.
    uint32_t bRow[4], bXor[4];
#pragma unroll
    for (int g = 0; g < 4; ++g) {
        int row = wn * 64 + g * 16 + ((lane >> 4) << 3) + (lane & 7);
        bRow[g] = (uint32_t)(row * 128);
        bXor[g] = (uint32_t)((row & 7) * 16);
    }
    const uint32_t bK = (((lane >> 3) & 1) * 16);

    float acc[4][8][4];
#pragma unroll
    for (int mi = 0; mi < 4; ++mi)
#pragma unroll
        for (int ni = 0; ni < 8; ++ni)
#pragma unroll
            for (int r = 0; r < 4; ++r) acc[mi][ni][r] = 0.0f;

    // ---- prologue: 2 stages in flight ----
    load_stage(0, 0);
    load_stage(1, 1);

    for (int it = 0; it < KITERS; ++it) {
        const int buf = it % STAGES;
        if (it == KITERS - 1) { CP_WAIT(0); } else { CP_WAIT(1); }
        __syncthreads();

        const int pf = it + STAGES - 1;
        if (pf < KITERS) load_stage(pf, pf % STAGES);

        const uint32_t abase = S + A_OFF + buf * A_STAGE;
        const uint32_t bbase = S + B_OFF + buf * B_STAGE;
#pragma unroll
        for (int kk = 0; kk < 4; ++kk) {
            uint32_t a[4][4];
#pragma unroll
            for (int mi = 0; mi < 4; ++mi)
                LDSM_X4(a[mi][0], a[mi][1], a[mi][2], a[mi][3],
                        abase + aRow[mi] + (((uint32_t)(kk * 32) + aK) ^ aXor[mi]));
            uint32_t b[4][4];
#pragma unroll
            for (int g = 0; g < 4; ++g)
                LDSM_X4(b[g][0], b[g][1], b[g][2], b[g][3],
                        bbase + bRow[g] + (((uint32_t)(kk * 32) + bK) ^ bXor[g]));
#pragma unroll
            for (int mi = 0; mi < 4; ++mi)
#pragma unroll
                for (int g = 0; g < 4; ++g) {
                    MMA16816(acc[mi][2 * g + 0], a[mi], b[g][0], b[g][1]);
                    MMA16816(acc[mi][2 * g + 1], a[mi], b[g][2], b[g][3]);
                }
        }
        // reuse of buf is gated by next iteration's __syncthreads()
    }

    // ---- epilogue ----
    const int r  = lane >> 2;
    const int c2 = (lane & 3) * 2;
    float bia[8][2];
#pragma unroll
    for (int ni = 0; ni < 8; ++ni) {
        bia[ni][0] = __ldg(&bias[n0 + wn * 64 + ni * 8 + c2 + 0]);
        bia[ni][1] = __ldg(&bias[n0 + wn * 64 + ni * 8 + c2 + 1]);
    }
#pragma unroll
    for (int mi = 0; mi < 4; ++mi) {
        const int mrow = m0 + wm * 64 + mi * 16 + r;
        float* o0 = out + (size_t)mrow * OUT_DIM + n0 + wn * 64;
        float* o1 = o0 + 8 * OUT_DIM;
#pragma unroll
        for (int ni = 0; ni < 8; ++ni) {
            const int nc = ni * 8 + c2;
            float2 v0 = {acc[mi][ni][0] + bia[ni][0], acc[mi][ni][1] + bia[ni][1]};
            float2 v1 = {acc[mi][ni][2] + bia[ni][0], acc[mi][ni][3] + bia[ni][1]};
            *reinterpret_cast<float2*>(o0 + nc) = v0;
            *reinterpret_cast<float2*>(o1 + nc) = v1;
        }
    }
}

// ---------------- launch ----------------
extern "C" void kernel_launch(void* const* d_in, const int* in_sizes, int n_in,
                              void* d_out, int out_size) {
    const float* x     = (const float*)d_in[0];
    const float* sw    = (const float*)d_in[1];
    const float* W     = (const float*)d_in[2];
    const float* bias  = (const float*)d_in[3];
    const float* knots = (const float*)d_in[4];
    float* out = (float*)d_out;

    build_a_kernel<<<(BATCH * IN_DIM) / 256, 256>>>(x, knots);
    build_b_kernel<<<(OUT_DIM * IN_DIM) / 256, 256>>>(sw, W);

    cudaFuncSetAttribute(kan_gemm_kernel, cudaFuncAttributeMaxDynamicSharedMemorySize, SMEM_BYTES);
    dim3 grid(OUT_DIM / BN, BATCH / BM);   // (4, 64)
    kan_gemm_kernel<<<grid, THREADS, SMEM_BYTES>>>(out, bias);
}

// round 3
// speedup vs baseline: 1.2637x; 1.2637x over previous
#include <cuda_runtime.h>
#include <cuda_fp16.h>
#include <cstdint>

// ---------------- problem constants ----------------
#define DEGREE   3
#define NB       7
#define NKNOTS   11
#define BATCH    8192
#define IN_DIM   1024
#define OUT_DIM  1024
#define KDIM     (IN_DIM * 8)   // 8192: 7 basis cols + 1 linear col per input

// GEMM tiling (baseline-PTX path: mma.sync m16n8k16, no tcgen05 on compute_103)
#define BM 128
#define BN 256
#define BK 64
#define STAGES 3
#define KITERS (KDIM / BK)      // 128
#define THREADS 256

#define A_STAGE (BM * BK * 2)   // 16384 B  (128 rows x 128B)
#define B_STAGE (BN * BK * 2)   // 32768 B  (256 rows x 128B)
#define A_OFF 0
#define B_OFF (STAGES * A_STAGE)                       // 49152
#define SMEM_BYTES (B_OFF + STAGES * B_STAGE + 1024)   // 144KB + align slack

// ---------------- scratch (device globals; no cudaMalloc allowed) ----------------
__device__ __half g_A[(size_t)BATCH * KDIM];    // 128 MB
__device__ __half g_B[(size_t)OUT_DIM * KDIM];  // 16 MB

// ---------------- PTX helpers (baseline ISA only) ----------------
__device__ __forceinline__ uint32_t smem_u32(const void* p) {
    uint32_t a;
    asm("{ .reg .u64 t; cvta.to.shared.u64 t, %1; cvt.u32.u64 %0, t; }" : "=r"(a) : "l"(p));
    return a;
}
__device__ __forceinline__ void cp_async16(uint32_t sdst, const void* gsrc) {
    asm volatile("cp.async.cg.shared.global [%0], [%1], 16;" :: "r"(sdst), "l"(gsrc));
}
#define CP_COMMIT() asm volatile("cp.async.commit_group;" ::: "memory")
#define CP_WAIT(n)  asm volatile("cp.async.wait_group %0;" :: "n"(n) : "memory")

#define LDSM_X4(r0, r1, r2, r3, addr) \
    asm volatile("ldmatrix.sync.aligned.m8n8.x4.shared.b16 {%0,%1,%2,%3}, [%4];" \
                 : "=r"(r0), "=r"(r1), "=r"(r2), "=r"(r3) : "r"(addr))

#define MMA16816(d, a, b0v, b1v) \
    asm volatile("mma.sync.aligned.m16n8k16.row.col.f32.f16.f16.f32 " \
                 "{%0,%1,%2,%3}, {%4,%5,%6,%7}, {%8,%9}, {%0,%1,%2,%3};" \
                 : "+f"((d)[0]), "+f"((d)[1]), "+f"((d)[2]), "+f"((d)[3]) \
                 : "r"((a)[0]), "r"((a)[1]), "r"((a)[2]), "r"((a)[3]), \
                   "r"(b0v), "r"(b1v))

// ---------------- basis helper (no divisions; uniform-knot reciprocals) ----------------
// Degree-0 indicators compare against the LOADED knot values (bit-compatible with
// the reference; the truncated basis is discontinuous at knots for j>=4, so the
// comparison values must match). Recurrence weights use exact constants 5, 2.5, 5/3
// (<=1e-6 relative perturbation vs fp32 knot differences; acts continuously).
__device__ __forceinline__ void eval_row(float xv, const float* kn, __half* h) {
    // fast tanh: 1 - 2/(exp(2x)+1); exact saturation at +-1 for |x| large
    float e = __expf(2.0f * xv);
    float t = 1.0f - __fdividef(2.0f, e + 1.0f);
    t = fminf(fmaxf(t, kn[0]), kn[NKNOTS - 1]);

    float bas[NB];
#pragma unroll
    for (int j = 0; j < NB; ++j)
        bas[j] = (t >= kn[j] && t < kn[j + 1]) ? 1.0f : 0.0f;

    const float C[3] = {5.0f, 2.5f, 5.0f / 3.0f};
#pragma unroll
    for (int d = 1; d <= DEGREE; ++d) {
        const float c = C[d - 1];
#pragma unroll
        for (int j = 0; j < NB; ++j) {
            float left  = (t - kn[j]) * c;
            float right = (kn[j + d + 1] - t) * c;
            float nxt = (j + 1 < NB) ? bas[j + 1] : 0.0f;
            bas[j] = left * bas[j] + right * nxt;   // ascending in-place is safe
        }
    }
#pragma unroll
    for (int k = 0; k < NB; ++k) h[k] = __float2half_rn(bas[k]);
    h[7] = __float2half_rn(xv);
}

// ---------------- prep kernel 1: A[b, i*8+k] = basis_k(tanh(x)) , x ----------------
// 4 elements per thread for ILP; 64B of contiguous stores per thread.
__global__ void __launch_bounds__(256) build_a_kernel(const float* __restrict__ x,
                                                      const float* __restrict__ knots) {
    int base = (blockIdx.x * blockDim.x + threadIdx.x) * 4;   // element index (b*IN + i)
    float kn[NKNOTS];
#pragma unroll
    for (int j = 0; j < NKNOTS; ++j) kn[j] = __ldg(&knots[j]);

    float4 xv = *reinterpret_cast<const float4*>(x + base);
    __half h[4][8];
    eval_row(xv.x, kn, h[0]);
    eval_row(xv.y, kn, h[1]);
    eval_row(xv.z, kn, h[2]);
    eval_row(xv.w, kn, h[3]);
#pragma unroll
    for (int e = 0; e < 4; ++e)
        *reinterpret_cast<uint4*>(&g_A[(size_t)(base + e) * 8]) =
            *reinterpret_cast<const uint4*>(h[e]);
}

// ---------------- prep kernel 2: Bmat[o, i*8+k] = spline_w[i,o,k] , W[o,i] ----------------
__global__ void build_b_kernel(const float* __restrict__ sw, const float* __restrict__ W) {
    int idx = blockIdx.x * blockDim.x + threadIdx.x;   // o*IN + i
    int o = idx >> 10, i = idx & 1023;
    const float* s = sw + ((size_t)i * OUT_DIM + o) * NB;
    __half h[8];
#pragma unroll
    for (int k = 0; k < NB; ++k) h[k] = __float2half_rn(__ldg(&s[k]));
    h[7] = __float2half_rn(__ldg(&W[(size_t)o * IN_DIM + i]));
    *reinterpret_cast<uint4*>(&g_B[(size_t)o * KDIM + (size_t)i * 8]) = *reinterpret_cast<const uint4*>(h);
}

// ---------------- GEMM: out[M,N] = A[M,K] * Bmat[N,K]^T + bias ----------------
// warps: 2(M) x 4(N), warp tile 64x64; mma m16n8k16 row.col, fp32 accum.
__global__ void __launch_bounds__(THREADS, 1)
kan_gemm_kernel(float* __restrict__ out, const float* __restrict__ bias) {
    extern __shared__ char smem_raw[];
    const uint32_t S = (smem_u32(smem_raw) + 1023u) & ~1023u;

    const int tid  = threadIdx.x;
    const int wid  = tid >> 5;
    const int lane = tid & 31;
    const int wm   = wid >> 2;      // 0..1
    const int wn   = wid & 3;       // 0..3
    const int n0 = blockIdx.x * BN;
    const int m0 = blockIdx.y * BM;

    const __half* gA = g_A + (size_t)m0 * KDIM;
    const __half* gB = g_B + (size_t)n0 * KDIM;

    // ---- async stage loader: swizzled rows of 128B (SW128: X ^= (row&7)*16) ----
    auto load_stage = [&](int it, int buf) {
        const int k0 = it * BK;
        const uint32_t ab = S + A_OFF + buf * A_STAGE;
#pragma unroll
        for (int t = 0; t < 4; ++t) {               // A: 1024 chunks of 16B
            int ch = tid + t * THREADS;
            int row = ch >> 3, cc = ch & 7;
            cp_async16(ab + row * 128 + ((cc * 16) ^ ((row & 7) * 16)),
                       gA + (size_t)row * KDIM + k0 + cc * 8);
        }
        const uint32_t bb = S + B_OFF + buf * B_STAGE;
#pragma unroll
        for (int t = 0; t < 8; ++t) {               // B: 2048 chunks of 16B
            int ch = tid + t * THREADS;
            int row = ch >> 3, cc = ch & 7;
            cp_async16(bb + row * 128 + ((cc * 16) ^ ((row & 7) * 16)),
                       gB + (size_t)row * KDIM + k0 + cc * 8);
        }
        CP_COMMIT();
    };

    // ---- precompute per-lane ldmatrix addressing ----
    uint32_t aRow[4], aXor[4];
#pragma unroll
    for (int mi = 0; mi < 4; ++mi) {
        int row = wm * 64 + mi * 16 + (lane & 15);
        aRow[mi] = (uint32_t)(row * 128);
        aXor[mi] = (uint32_t)((row & 7) * 16);
    }
    const uint32_t aK = ((lane >> 4) * 16);

    uint32_t bRow[4], bXor[4];
#pragma unroll
    for (int g = 0; g < 4; ++g) {
        int row = wn * 64 + g * 16 + ((lane >> 4) << 3) + (lane & 7);
        bRow[g] = (uint32_t)(row * 128);
        bXor[g] = (uint32_t)((row & 7) * 16);
    }
    const uint32_t bK = (((lane >> 3) & 1) * 16);

    float acc[4][8][4];
#pragma unroll
    for (int mi = 0; mi < 4; ++mi)
#pragma unroll
        for (int ni = 0; ni < 8; ++ni)
#pragma unroll
            for (int r = 0; r < 4; ++r) acc[mi][ni][r] = 0.0f;

    load_stage(0, 0);
    load_stage(1, 1);

    for (int it = 0; it < KITERS; ++it) {
        const int buf = it % STAGES;
        if (it == KITERS - 1) { CP_WAIT(0); } else { CP_WAIT(1); }
        __syncthreads();

        const int pf = it + STAGES - 1;
        if (pf < KITERS) load_stage(pf, pf % STAGES);

        const uint32_t abase = S + A_OFF + buf * A_STAGE;
        const uint32_t bbase = S + B_OFF + buf * B_STAGE;
#pragma unroll
        for (int kk = 0; kk < 4; ++kk) {
            uint32_t a[4][4];
#pragma unroll
            for (int mi = 0; mi < 4; ++mi)
                LDSM_X4(a[mi][0], a[mi][1], a[mi][2], a[mi][3],
                        abase + aRow[mi] + (((uint32_t)(kk * 32) + aK) ^ aXor[mi]));
            uint32_t b[4][4];
#pragma unroll
            for (int g = 0; g < 4; ++g)
                LDSM_X4(b[g][0], b[g][1], b[g][2], b[g][3],
                        bbase + bRow[g] + (((uint32_t)(kk * 32) + bK) ^ bXor[g]));
#pragma unroll
            for (int mi = 0; mi < 4; ++mi)
#pragma unroll
                for (int g = 0; g < 4; ++g) {
                    MMA16816(acc[mi][2 * g + 0], a[mi], b[g][0], b[g][1]);
                    MMA16816(acc[mi][2 * g + 1], a[mi], b[g][2], b[g][3]);
                }
        }
    }

    // ---- epilogue ----
    const int r  = lane >> 2;
    const int c2 = (lane & 3) * 2;
    float bia[8][2];
#pragma unroll
    for (int ni = 0; ni < 8; ++ni) {
        bia[ni][0] = __ldg(&bias[n0 + wn * 64 + ni * 8 + c2 + 0]);
        bia[ni][1] = __ldg(&bias[n0 + wn * 64 + ni * 8 + c2 + 1]);
    }
#pragma unroll
    for (int mi = 0; mi < 4; ++mi) {
        const int mrow = m0 + wm * 64 + mi * 16 + r;
        float* o0 = out + (size_t)mrow * OUT_DIM + n0 + wn * 64;
        float* o1 = o0 + 8 * OUT_DIM;
#pragma unroll
        for (int ni = 0; ni < 8; ++ni) {
            const int nc = ni * 8 + c2;
            float2 v0 = {acc[mi][ni][0] + bia[ni][0], acc[mi][ni][1] + bia[ni][1]};
            float2 v1 = {acc[mi][ni][2] + bia[ni][0], acc[mi][ni][3] + bia[ni][1]};
            *reinterpret_cast<float2*>(o0 + nc) = v0;
            *reinterpret_cast<float2*>(o1 + nc) = v1;
        }
    }
}

// ---------------- launch ----------------
extern "C" void kernel_launch(void* const* d_in, const int* in_sizes, int n_in,
                              void* d_out, int out_size) {
    const float* x     = (const float*)d_in[0];
    const float* sw    = (const float*)d_in[1];
    const float* W     = (const float*)d_in[2];
    const float* bias  = (const float*)d_in[3];
    const float* knots = (const float*)d_in[4];
    float* out = (float*)d_out;

    build_a_kernel<<<(BATCH * IN_DIM) / (256 * 4), 256>>>(x, knots);
    build_b_kernel<<<(OUT_DIM * IN_DIM) / 256, 256>>>(sw, W);

    cudaFuncSetAttribute(kan_gemm_kernel, cudaFuncAttributeMaxDynamicSharedMemorySize, SMEM_BYTES);
    dim3 grid(OUT_DIM / BN, BATCH / BM);   // (4, 64)
    kan_gemm_kernel<<<grid, THREADS, SMEM_BYTES>>>(out, bias);
}

// round 4
// speedup vs baseline: 1.4045x; 1.1114x over previous
#include <cuda_runtime.h>
#include <cuda_fp16.h>
#include <cstdint>

// ---------------- problem constants ----------------
#define DEGREE   3
#define NB       7
#define NKNOTS   11
#define BATCH    8192
#define IN_DIM   1024
#define OUT_DIM  1024
#define KDIM     (IN_DIM * 8)   // 8192: 7 basis cols + 1 linear col per input

// GEMM tiling: 64x128 CTA tile, 4 warps (2x2) of 32x64, 3-stage cp.async pipeline.
// 1024 CTAs -> 98.8% wave efficiency on 148 SMs; 72KB smem -> 3 CTAs/SM resident.
#define BM 64
#define BN 128
#define BK 64
#define STAGES 3
#define KITERS (KDIM / BK)      // 128
#define THREADS 128

#define A_STAGE (BM * BK * 2)   // 8192 B   (64 rows x 128B)
#define B_STAGE (BN * BK * 2)   // 16384 B  (128 rows x 128B)
#define A_OFF 0
#define B_OFF (STAGES * A_STAGE)                       // 24576
#define SMEM_BYTES (B_OFF + STAGES * B_STAGE + 1024)   // 73728 + align slack

// ---------------- scratch (device globals; no cudaMalloc allowed) ----------------
__device__ __half g_A[(size_t)BATCH * KDIM];    // 128 MB
__device__ __half g_B[(size_t)OUT_DIM * KDIM];  // 16 MB

// ---------------- PTX helpers (baseline ISA only) ----------------
__device__ __forceinline__ uint32_t smem_u32(const void* p) {
    uint32_t a;
    asm("{ .reg .u64 t; cvta.to.shared.u64 t, %1; cvt.u32.u64 %0, t; }" : "=r"(a) : "l"(p));
    return a;
}
__device__ __forceinline__ void cp_async16(uint32_t sdst, const void* gsrc) {
    asm volatile("cp.async.cg.shared.global [%0], [%1], 16;" :: "r"(sdst), "l"(gsrc));
}
#define CP_COMMIT() asm volatile("cp.async.commit_group;" ::: "memory")
#define CP_WAIT(n)  asm volatile("cp.async.wait_group %0;" :: "n"(n) : "memory")

#define LDSM_X4(r0, r1, r2, r3, addr) \
    asm volatile("ldmatrix.sync.aligned.m8n8.x4.shared.b16 {%0,%1,%2,%3}, [%4];" \
                 : "=r"(r0), "=r"(r1), "=r"(r2), "=r"(r3) : "r"(addr))

#define MMA16816(d, a, b0v, b1v) \
    asm volatile("mma.sync.aligned.m16n8k16.row.col.f32.f16.f16.f32 " \
                 "{%0,%1,%2,%3}, {%4,%5,%6,%7}, {%8,%9}, {%0,%1,%2,%3};" \
                 : "+f"((d)[0]), "+f"((d)[1]), "+f"((d)[2]), "+f"((d)[3]) \
                 : "r"((a)[0]), "r"((a)[1]), "r"((a)[2]), "r"((a)[3]), \
                   "r"(b0v), "r"(b1v))

// ---------------- basis helper (no divisions; uniform-knot reciprocals) ----------------
__device__ __forceinline__ void eval_row(float xv, const float* kn, __half* h) {
    float e = __expf(2.0f * xv);
    float t = 1.0f - __fdividef(2.0f, e + 1.0f);
    t = fminf(fmaxf(t, kn[0]), kn[NKNOTS - 1]);

    float bas[NB];
#pragma unroll
    for (int j = 0; j < NB; ++j)
        bas[j] = (t >= kn[j] && t < kn[j + 1]) ? 1.0f : 0.0f;

    const float C[3] = {5.0f, 2.5f, 5.0f / 3.0f};
#pragma unroll
    for (int d = 1; d <= DEGREE; ++d) {
        const float c = C[d - 1];
#pragma unroll
        for (int j = 0; j < NB; ++j) {
            float left  = (t - kn[j]) * c;
            float right = (kn[j + d + 1] - t) * c;
            float nxt = (j + 1 < NB) ? bas[j + 1] : 0.0f;
            bas[j] = left * bas[j] + right * nxt;
        }
    }
#pragma unroll
    for (int k = 0; k < NB; ++k) h[k] = __float2half_rn(bas[k]);
    h[7] = __float2half_rn(xv);
}

// ---------------- prep kernel 1 ----------------
__global__ void __launch_bounds__(256) build_a_kernel(const float* __restrict__ x,
                                                      const float* __restrict__ knots) {
    int base = (blockIdx.x * blockDim.x + threadIdx.x) * 4;
    float kn[NKNOTS];
#pragma unroll
    for (int j = 0; j < NKNOTS; ++j) kn[j] = __ldg(&knots[j]);

    float4 xv = *reinterpret_cast<const float4*>(x + base);
    __half h[4][8];
    eval_row(xv.x, kn, h[0]);
    eval_row(xv.y, kn, h[1]);
    eval_row(xv.z, kn, h[2]);
    eval_row(xv.w, kn, h[3]);
#pragma unroll
    for (int e = 0; e < 4; ++e)
        *reinterpret_cast<uint4*>(&g_A[(size_t)(base + e) * 8]) =
            *reinterpret_cast<const uint4*>(h[e]);
}

// ---------------- prep kernel 2 ----------------
__global__ void build_b_kernel(const float* __restrict__ sw, const float* __restrict__ W) {
    int idx = blockIdx.x * blockDim.x + threadIdx.x;   // o*IN + i
    int o = idx >> 10, i = idx & 1023;
    const float* s = sw + ((size_t)i * OUT_DIM + o) * NB;
    __half h[8];
#pragma unroll
    for (int k = 0; k < NB; ++k) h[k] = __float2half_rn(__ldg(&s[k]));
    h[7] = __float2half_rn(__ldg(&W[(size_t)o * IN_DIM + i]));
    *reinterpret_cast<uint4*>(&g_B[(size_t)o * KDIM + (size_t)i * 8]) = *reinterpret_cast<const uint4*>(h);
}

// ---------------- GEMM: out[M,N] = A[M,K] * Bmat[N,K]^T + bias ----------------
// warps: 2(M) x 2(N), warp tile 32x64; mma m16n8k16 row.col, fp32 accum.
__global__ void __launch_bounds__(THREADS)
kan_gemm_kernel(float* __restrict__ out, const float* __restrict__ bias) {
    extern __shared__ char smem_raw[];
    const uint32_t S = (smem_u32(smem_raw) + 1023u) & ~1023u;

    const int tid  = threadIdx.x;
    const int wid  = tid >> 5;
    const int lane = tid & 31;
    const int wm   = wid >> 1;      // 0..1
    const int wn   = wid & 1;       // 0..1
    const int n0 = blockIdx.x * BN;
    const int m0 = blockIdx.y * BM;

    const __half* gA = g_A + (size_t)m0 * KDIM;
    const __half* gB = g_B + (size_t)n0 * KDIM;

    // ---- async stage loader: swizzled rows of 128B (SW128: X ^= (row&7)*16) ----
    auto load_stage = [&](int it, int buf) {
        const int k0 = it * BK;
        const uint32_t ab = S + A_OFF + buf * A_STAGE;
#pragma unroll
        for (int t = 0; t < 4; ++t) {               // A: 512 chunks of 16B
            int ch = tid + t * THREADS;
            int row = ch >> 3, cc = ch & 7;
            cp_async16(ab + row * 128 + ((cc * 16) ^ ((row & 7) * 16)),
                       gA + (size_t)row * KDIM + k0 + cc * 8);
        }
        const uint32_t bb = S + B_OFF + buf * B_STAGE;
#pragma unroll
        for (int t = 0; t < 8; ++t) {               // B: 1024 chunks of 16B
            int ch = tid + t * THREADS;
            int row = ch >> 3, cc = ch & 7;
            cp_async16(bb + row * 128 + ((cc * 16) ^ ((row & 7) * 16)),
                       gB + (size_t)row * KDIM + k0 + cc * 8);
        }
        CP_COMMIT();
    };

    // ---- per-lane ldmatrix addressing ----
    uint32_t aRow[2], aXor[2];
#pragma unroll
    for (int mi = 0; mi < 2; ++mi) {
        int row = wm * 32 + mi * 16 + (lane & 15);
        aRow[mi] = (uint32_t)(row * 128);
        aXor[mi] = (uint32_t)((row & 7) * 16);
    }
    const uint32_t aK = ((lane >> 4) * 16);

    uint32_t bRow[4], bXor[4];
#pragma unroll
    for (int g = 0; g < 4; ++g) {
        int row = wn * 64 + g * 16 + ((lane >> 4) << 3) + (lane & 7);
        bRow[g] = (uint32_t)(row * 128);
        bXor[g] = (uint32_t)((row & 7) * 16);
    }
    const uint32_t bK = (((lane >> 3) & 1) * 16);

    float acc[2][8][4];
#pragma unroll
    for (int mi = 0; mi < 2; ++mi)
#pragma unroll
        for (int ni = 0; ni < 8; ++ni)
#pragma unroll
            for (int r = 0; r < 4; ++r) acc[mi][ni][r] = 0.0f;

    load_stage(0, 0);
    load_stage(1, 1);

    for (int it = 0; it < KITERS; ++it) {
        const int buf = it % STAGES;
        if (it == KITERS - 1) { CP_WAIT(0); } else { CP_WAIT(1); }
        __syncthreads();

        const int pf = it + STAGES - 1;
        if (pf < KITERS) load_stage(pf, pf % STAGES);

        const uint32_t abase = S + A_OFF + buf * A_STAGE;
        const uint32_t bbase = S + B_OFF + buf * B_STAGE;
#pragma unroll
        for (int kk = 0; kk < 4; ++kk) {
            uint32_t a[2][4];
#pragma unroll
            for (int mi = 0; mi < 2; ++mi)
                LDSM_X4(a[mi][0], a[mi][1], a[mi][2], a[mi][3],
                        abase + aRow[mi] + (((uint32_t)(kk * 32) + aK) ^ aXor[mi]));
            uint32_t b[4][4];
#pragma unroll
            for (int g = 0; g < 4; ++g)
                LDSM_X4(b[g][0], b[g][1], b[g][2], b[g][3],
                        bbase + bRow[g] + (((uint32_t)(kk * 32) + bK) ^ bXor[g]));
#pragma unroll
            for (int mi = 0; mi < 2; ++mi)
#pragma unroll
                for (int g = 0; g < 4; ++g) {
                    MMA16816(acc[mi][2 * g + 0], a[mi], b[g][0], b[g][1]);
                    MMA16816(acc[mi][2 * g + 1], a[mi], b[g][2], b[g][3]);
                }
        }
    }

    // ---- epilogue ----
    const int r  = lane >> 2;
    const int c2 = (lane & 3) * 2;
    float bia[8][2];
#pragma unroll
    for (int ni = 0; ni < 8; ++ni) {
        bia[ni][0] = __ldg(&bias[n0 + wn * 64 + ni * 8 + c2 + 0]);
        bia[ni][1] = __ldg(&bias[n0 + wn * 64 + ni * 8 + c2 + 1]);
    }
#pragma unroll
    for (int mi = 0; mi < 2; ++mi) {
        const int mrow = m0 + wm * 32 + mi * 16 + r;
        float* o0 = out + (size_t)mrow * OUT_DIM + n0 + wn * 64;
        float* o1 = o0 + 8 * OUT_DIM;
#pragma unroll
        for (int ni = 0; ni < 8; ++ni) {
            const int nc = ni * 8 + c2;
            float2 v0 = {acc[mi][ni][0] + bia[ni][0], acc[mi][ni][1] + bia[ni][1]};
            float2 v1 = {acc[mi][ni][2] + bia[ni][0], acc[mi][ni][3] + bia[ni][1]};
            *reinterpret_cast<float2*>(o0 + nc) = v0;
            *reinterpret_cast<float2*>(o1 + nc) = v1;
        }
    }
}

// ---------------- launch ----------------
extern "C" void kernel_launch(void* const* d_in, const int* in_sizes, int n_in,
                              void* d_out, int out_size) {
    const float* x     = (const float*)d_in[0];
    const float* sw    = (const float*)d_in[1];
    const float* W     = (const float*)d_in[2];
    const float* bias  = (const float*)d_in[3];
    const float* knots = (const float*)d_in[4];
    float* out = (float*)d_out;

    build_a_kernel<<<(BATCH * IN_DIM) / (256 * 4), 256>>>(x, knots);
    build_b_kernel<<<(OUT_DIM * IN_DIM) / 256, 256>>>(sw, W);

    cudaFuncSetAttribute(kan_gemm_kernel, cudaFuncAttributeMaxDynamicSharedMemorySize, SMEM_BYTES);
    dim3 grid(OUT_DIM / BN, BATCH / BM);   // (8, 128) = 1024 CTAs
    kan_gemm_kernel<<<grid, THREADS, SMEM_BYTES>>>(out, bias);
}